// round 12
// baseline (speedup 1.0000x reference)
#include <cuda_runtime.h>
#include <cstdint>

// GraphAttention: out[b,t,:] = LayerNorm(node + sum_k att_k * neigh_k)
//   att_k = dot(neigh_k, node)/15, neigh_k masked (0/1).
// Inputs: node_ids i32[B*3], neighbor_ids i32[B*3*64], neighbor_mask i32[B*3*64],
//         emb f32[500000*128], gamma f32[128], beta f32[128]. Output f32[B*3*128].
//
// R12: bulk-copy (TMA-pipe) gather HBM->SMEM with mbarrier completion, then
// compute from SMEM. Decouples DRAM latency from warp execution entirely.

#define DDIM  128
#define KNB   64
#define NWARP 4
#define KPW   (KNB / NWARP)   // 16 neighbors per warp

__device__ __forceinline__ uint32_t smem_u32(const void* p) {
    return (uint32_t)__cvta_generic_to_shared(p);
}

__global__ __launch_bounds__(128, 6)
void ga_kernel(const int* __restrict__ node_ids,
               const int* __restrict__ nbr_ids,
               const int* __restrict__ nbr_mask,
               const float* __restrict__ emb,
               const float* __restrict__ gamma,
               const float* __restrict__ beta,
               float* __restrict__ out,
               int n_rows)
{
    const int bt = blockIdx.x;
    if (bt >= n_rows) return;

    const int tid = threadIdx.x;
    const int w   = tid >> 5;
    const int l   = tid & 31;

    __shared__ __align__(128) float srow[NWARP][KPW][DDIM];  // 32 KB row buffer
    __shared__ float    sacc[NWARP][DDIM];
    __shared__ float    sred[2 * NWARP];
    __shared__ int      slist[NWARP][KPW];
    __shared__ __align__(8) unsigned long long smbar[NWARP];

    // Per-warp mbarrier init (count=1, tx-based completion).
    if (l == 0) {
        uint32_t mb = smem_u32(&smbar[w]);
        asm volatile("mbarrier.init.shared.b64 [%0], %1;" :: "r"(mb), "r"(1));
        asm volatile("fence.mbarrier_init.release.cluster;" ::: "memory");
    }
    __syncwarp();

    // Node row: lane l holds dims [4l, 4l+4)
    const size_t nid = (size_t)node_ids[bt];
    const float4 n4 = reinterpret_cast<const float4*>(emb + nid * DDIM)[l];

    const int* kid = nbr_ids  + (size_t)bt * KNB + w * KPW;
    const int* km  = nbr_mask + (size_t)bt * KNB + w * KPW;

    // ---- Warp compaction of unmasked neighbor ids into a dense smem list ----
    int myid = 0, mym = 0;
    if (l < KPW) { mym = __ldg(km + l); myid = __ldg(kid + l); }
    const unsigned bal = __ballot_sync(0xffffffffu, mym != 0);
    const int cnt = __popc(bal);
    const int pos = __popc(bal & ((1u << l) - 1u));
    if (mym) slist[w][pos] = myid;
    const int cnt_pad = (cnt + 3) & ~3;            // pad to group of 4
    if (l >= cnt && l < cnt_pad) slist[w][l] = (int)nid;   // L2-hot pad rows
    __syncwarp();

    // ---- Bulk gather: lane j (< cnt_pad) copies its whole 512B row via the
    // TMA/bulk pipe into smem; completion via per-warp mbarrier tx-count. ----
    const uint32_t mb = smem_u32(&smbar[w]);
    if (l == 0) {
        asm volatile("mbarrier.arrive.expect_tx.shared.b64 _, [%0], %1;"
                     :: "r"(mb), "r"((uint32_t)(cnt_pad * 512)) : "memory");
    }
    __syncwarp();
    if (l < cnt_pad) {
        const float* src = emb + (size_t)slist[w][l] * DDIM;
        const uint32_t dst = smem_u32(&srow[w][l][0]);
        asm volatile(
            "cp.async.bulk.shared::cluster.global.mbarrier::complete_tx::bytes "
            "[%0], [%1], %2, [%3];"
            :: "r"(dst), "l"(src), "r"(512), "r"(mb) : "memory");
    }

    // Sleep until all rows have landed (phase parity 0).
    {
        uint32_t done;
        asm volatile(
            "{\n\t.reg .pred p;\n\t"
            "mbarrier.try_wait.parity.shared.b64 p, [%1], %2;\n\t"
            "selp.b32 %0, 1, 0, p;\n\t}"
            : "=r"(done) : "r"(mb), "r"(0) : "memory");
        while (!done) {
            asm volatile(
                "{\n\t.reg .pred p;\n\t"
                "mbarrier.try_wait.parity.shared.b64 p, [%1], %2, 0x989680;\n\t"
                "selp.b32 %0, 1, 0, p;\n\t}"
                : "=r"(done) : "r"(mb), "r"(0) : "memory");
        }
    }

    // ---- Compute from SMEM: 4 rows per group, R5 structure, LDS.128 reads ----
    float4 acc = make_float4(0.f, 0.f, 0.f, 0.f);
    const int groups = cnt_pad >> 2;

    for (int g = 0; g < groups; g++) {
        const int jb = 4 * g;
        const float4 v0 = reinterpret_cast<const float4*>(&srow[w][jb + 0][0])[l];
        const float4 v1 = reinterpret_cast<const float4*>(&srow[w][jb + 1][0])[l];
        const float4 v2 = reinterpret_cast<const float4*>(&srow[w][jb + 2][0])[l];
        const float4 v3 = reinterpret_cast<const float4*>(&srow[w][jb + 3][0])[l];

        float p0 = n4.x*v0.x + n4.y*v0.y + n4.z*v0.z + n4.w*v0.w;
        float p1 = n4.x*v1.x + n4.y*v1.y + n4.z*v1.z + n4.w*v1.w;
        float p2 = n4.x*v2.x + n4.y*v2.y + n4.z*v2.z + n4.w*v2.w;
        float p3 = n4.x*v3.x + n4.y*v3.y + n4.z*v3.z + n4.w*v3.w;
        #pragma unroll
        for (int off = 16; off > 0; off >>= 1) {
            p0 += __shfl_xor_sync(0xffffffffu, p0, off);
            p1 += __shfl_xor_sync(0xffffffffu, p1, off);
            p2 += __shfl_xor_sync(0xffffffffu, p2, off);
            p3 += __shfl_xor_sync(0xffffffffu, p3, off);
        }
        const float a0 = (jb + 0 < cnt) ? p0 * (1.0f / 15.0f) : 0.f;
        const float a1 = (jb + 1 < cnt) ? p1 * (1.0f / 15.0f) : 0.f;
        const float a2 = (jb + 2 < cnt) ? p2 * (1.0f / 15.0f) : 0.f;
        const float a3 = (jb + 3 < cnt) ? p3 * (1.0f / 15.0f) : 0.f;

        acc.x = fmaf(a0, v0.x, fmaf(a1, v1.x, fmaf(a2, v2.x, fmaf(a3, v3.x, acc.x))));
        acc.y = fmaf(a0, v0.y, fmaf(a1, v1.y, fmaf(a2, v2.y, fmaf(a3, v3.y, acc.y))));
        acc.z = fmaf(a0, v0.z, fmaf(a1, v1.z, fmaf(a2, v2.z, fmaf(a3, v3.z, acc.z))));
        acc.w = fmaf(a0, v0.w, fmaf(a1, v1.w, fmaf(a2, v2.w, fmaf(a3, v3.w, acc.w))));
    }

    reinterpret_cast<float4*>(&sacc[w][0])[l] = acc;
    __syncthreads();

    // Thread tid owns dim d = tid.
    const int d = tid;
    const float nd = __ldg(emb + nid * DDIM + d);   // L1/L2 hit (row already fetched)
    float x = nd + sacc[0][d] + sacc[1][d] + sacc[2][d] + sacc[3][d];

    // Block-level LayerNorm reduction over 128 values
    float s = x, s2 = x * x;
    #pragma unroll
    for (int off = 16; off > 0; off >>= 1) {
        s  += __shfl_xor_sync(0xffffffffu, s,  off);
        s2 += __shfl_xor_sync(0xffffffffu, s2, off);
    }
    if (l == 0) { sred[w] = s; sred[NWARP + w] = s2; }
    __syncthreads();

    const float ss  = sred[0] + sred[1] + sred[2] + sred[3];
    const float ss2 = sred[NWARP + 0] + sred[NWARP + 1] + sred[NWARP + 2] + sred[NWARP + 3];

    const float mu  = ss * (1.0f / DDIM);
    const float var = ss2 * (1.0f / DDIM) - mu * mu;
    const float inv = rsqrtf(var + 1e-5f);

    out[(size_t)bt * DDIM + d] = (x - mu) * inv * gamma[d] + beta[d];
}

extern "C" void kernel_launch(void* const* d_in, const int* in_sizes, int n_in,
                              void* d_out, int out_size)
{
    const int*   node_ids = (const int*)  d_in[0];
    const int*   nbr_ids  = (const int*)  d_in[1];
    const int*   nbr_mask = (const int*)  d_in[2];
    const float* emb      = (const float*)d_in[3];
    const float* gamma    = (const float*)d_in[4];
    const float* beta     = (const float*)d_in[5];
    float*       out      = (float*)d_out;

    const int n_rows = in_sizes[0];          // B*3 = 12288
    ga_kernel<<<n_rows, 128>>>(node_ids, nbr_ids, nbr_mask, emb, gamma, beta,
                               out, n_rows);
}